// round 3
// baseline (speedup 1.0000x reference)
#include <cuda_runtime.h>
#include <cuda_bf16.h>

// Problem constants
#define BB   64      // batch (inputs)
#define MM   256     // modes
#define KK   4096    // spatial (64*64)

#define KC      128  // K per CTA chunk
#define KSPLIT  32   // KK / KC
#define MT      32   // modes per CTA (one per lane)
#define MTILES  8    // MM / MT
#define NTHR    128  // 4 warps
#define EPS_C   0.0009f

// Deterministic scratch (no cudaMalloc allowed)
__device__ __align__(16) float g_dot[KSPLIT * BB * MM];   // [s][b][m]  2 MB
__device__ __align__(16) float g_fss[KSPLIT * BB];        // [s][b]
__device__ __align__(16) float g_mss[KSPLIT * MM];        // [s][m]
__device__ unsigned int g_cnt[MTILES];                    // zero-init; reset by finalizer

__device__ __forceinline__ unsigned long long fma2(unsigned long long a,
                                                   unsigned long long b,
                                                   unsigned long long c) {
    unsigned long long d;
    asm("fma.rn.f32x2 %0, %1, %2, %3;" : "=l"(d) : "l"(a), "l"(b), "l"(c));
    return d;
}

__device__ __forceinline__ float2 ull2f2(unsigned long long u) {
    float2 f;
    f.x = __uint_as_float((unsigned int)u);
    f.y = __uint_as_float((unsigned int)(u >> 32));
    return f;
}

__device__ __forceinline__ float metric_of(float dot, float fss, float mss) {
    float fn = sqrtf(fss);
    float mn = sqrtf(mss);
    float cc = dot / (fn * mn);
    float dn = sqrtf(fmaxf(2.f - 2.f * cc, 0.f));
    float lum = (2.f * fn * mn + EPS_C) / (fss + mss + EPS_C);
    return (1.f - (2.f - dn) * 0.5f * sqrtf(lum)) * 2.f;
}

// Fused kernel. CTA (mt, ks): partial dot[b=0..63][m=mt*32..+31] over k-chunk ks,
// plus partial norms. Last CTA of each mt column reduces K-splits, computes the
// metric and atomicMin's into out (nonneg floats -> uint order == float order).
__global__ __launch_bounds__(NTHR)
void fused_kernel(const float* __restrict__ inp,
                  const float* __restrict__ mds,
                  unsigned int* __restrict__ outu) {
    __shared__ float As[BB * KC];   // 32 KB, k-major, unswizzled
    __shared__ float Bs[MT * KC];   // 16 KB, k-major, kq ^ (m&7) swizzle
    __shared__ float s_fss[BB];
    __shared__ int   s_flag;

    const int mt = blockIdx.x;
    const int ks = blockIdx.y;
    const int kbase = ks * KC;
    const int mbase = mt * MT;
    const int tid  = threadIdx.x;
    const int lane = tid & 31;
    const int w    = tid >> 5;      // 0..3

    float4* As4 = reinterpret_cast<float4*>(As);
    float4* Bs4 = reinterpret_cast<float4*>(Bs);

    // ---- stage A: 64 rows x 32 float4, coalesced ----
#pragma unroll
    for (int i = 0; i < 16; ++i) {
        int j  = i * NTHR + tid;
        int b  = j >> 5;
        int kq = j & 31;
        As4[b * 32 + kq] =
            *(reinterpret_cast<const float4*>(inp + (size_t)b * KK + kbase) + kq);
    }
    // ---- stage B: 32 rows x 32 float4, swizzled ----
#pragma unroll
    for (int i = 0; i < 8; ++i) {
        int j  = i * NTHR + tid;
        int m  = j >> 5;
        int kq = j & 31;
        Bs4[m * 32 + (kq ^ (m & 7))] =
            *(reinterpret_cast<const float4*>(mds + (size_t)(mbase + m) * KK + kbase) + kq);
    }
    __syncthreads();

    // ---- main loop: lane owns m=lane; warp w owns b-rows 16w..16w+15 ----
    const int c = lane & 7;
    const ulonglong2* As2 = reinterpret_cast<const ulonglong2*>(As);
    const ulonglong2* Bs2 = reinterpret_cast<const ulonglong2*>(Bs);

    unsigned long long acc[16];
#pragma unroll
    for (int r = 0; r < 16; ++r) acc[r] = 0ull;

#pragma unroll 2
    for (int kq = 0; kq < 32; ++kq) {
        ulonglong2 bv = Bs2[lane * 32 + (kq ^ c)];   // lane-distinct, 4-phase floor
#pragma unroll
        for (int r = 0; r < 16; ++r) {
            ulonglong2 av = As2[(16 * w + r) * 32 + kq];  // warp-broadcast, 1 phase
            acc[r] = fma2(av.x, bv.x, acc[r]);
            acc[r] = fma2(av.y, bv.y, acc[r]);
        }
    }

    // ---- epilogue: reduce k-parity, coalesced partial-dot store ----
#pragma unroll
    for (int r = 0; r < 16; ++r) {
        float2 e = ull2f2(acc[r]);
        g_dot[((size_t)ks * BB + 16 * w + r) * MM + mbase + lane] = e.x + e.y;
    }

    // ---- partial squared norms ----
    // mode norms (this CTA's slice): warp w handles m rows 8w..8w+7
#pragma unroll
    for (int r = 0; r < 8; ++r) {
        int m = 8 * w + r;
        float4 v = Bs4[m * 32 + (lane ^ (m & 7))];
        float s = v.x * v.x + v.y * v.y + v.z * v.z + v.w * v.w;
#pragma unroll
        for (int o = 16; o > 0; o >>= 1) s += __shfl_xor_sync(0xffffffffu, s, o);
        if (lane == 0) g_mss[ks * MM + mbase + m] = s;
    }
    // input norms: EVERY CTA writes (bitwise-identical duplicates across mt),
    // so a column's finalizer only depends on its own 32 CTAs.
#pragma unroll
    for (int r = 0; r < 16; ++r) {
        int b = 16 * w + r;
        float4 v = As4[b * 32 + lane];
        float s = v.x * v.x + v.y * v.y + v.z * v.z + v.w * v.w;
#pragma unroll
        for (int o = 16; o > 0; o >>= 1) s += __shfl_xor_sync(0xffffffffu, s, o);
        if (lane == 0) g_fss[ks * BB + b] = s;
    }

    // ---- last-CTA-per-column handoff ----
    __syncthreads();
    if (tid == 0) {
        __threadfence();
        unsigned int old = atomicAdd(&g_cnt[mt], 1u);
        s_flag = (old == KSPLIT - 1);
    }
    __syncthreads();
    if (!s_flag) return;
    __threadfence();

    // ---- finalize this column: 64 b x 32 m ----
    // stage full fss[b] in smem (threads 0..63)
    if (tid < BB) {
        float s = 0.f;
#pragma unroll
        for (int ss = 0; ss < KSPLIT; ++ss) s += g_fss[ss * BB + tid];
        s_fss[tid] = s;
    }
    __syncthreads();

    const float4* dot4 = reinterpret_cast<const float4*>(g_dot);
    const float4* mss4 = reinterpret_cast<const float4*>(g_mss);

    // tasks: (b, m-quad). 64 b x 8 quads = 512 tasks, 4 per thread.
#pragma unroll
    for (int i = 0; i < 4; ++i) {
        int task = tid + NTHR * i;
        int b = task >> 3;
        int q = task & 7;                 // float4 index within the 32-mode slice
        int col4 = (mbase >> 2) + q;      // float4 column in [0,64)

        float4 d = make_float4(0.f, 0.f, 0.f, 0.f);
        float4 ms = make_float4(0.f, 0.f, 0.f, 0.f);
#pragma unroll 8
        for (int ss = 0; ss < KSPLIT; ++ss) {
            float4 dv = dot4[((size_t)ss * BB + b) * (MM / 4) + col4];
            float4 mv = mss4[ss * (MM / 4) + col4];
            d.x += dv.x; d.y += dv.y; d.z += dv.z; d.w += dv.w;
            ms.x += mv.x; ms.y += mv.y; ms.z += mv.z; ms.w += mv.w;
        }
        float fss = s_fss[b];
        float v0 = metric_of(d.x, fss, ms.x);
        float v1 = metric_of(d.y, fss, ms.y);
        float v2 = metric_of(d.z, fss, ms.z);
        float v3 = metric_of(d.w, fss, ms.w);
        float v = fminf(fminf(v0, v1), fminf(v2, v3));
        atomicMin(&outu[b], __float_as_uint(v));   // nonneg: uint order == float order
    }

    __syncthreads();
    if (tid == 0) g_cnt[mt] = 0;   // reset for next graph replay
}

extern "C" void kernel_launch(void* const* d_in, const int* in_sizes, int n_in,
                              void* d_out, int out_size) {
    const float* inp = (const float*)d_in[0];
    const float* mds = (const float*)d_in[1];
    if (in_sizes[0] > in_sizes[1]) {   // identify by element count
        const float* t = inp; inp = mds; mds = t;
    }

    // init out to +big (0x7f7f7f7f ~ 3.4e38, positive) for the atomicMin
    cudaMemsetAsync(d_out, 0x7f, (size_t)out_size * sizeof(float));

    dim3 grid(MTILES, KSPLIT);
    fused_kernel<<<grid, NTHR>>>(inp, mds, (unsigned int*)d_out);
}